// round 14
// baseline (speedup 1.0000x reference)
#include <cuda_runtime.h>
#include <math.h>
#include <stdint.h>

// ---------------------------------------------------------------------------
// LocalSparseAttention — tf32 mma.sync, fragment-pair-packed operand layouts
//   B=2, N=65536 (256x256), C=256, window=16 (256 tok/window), heads=8, hd=32
//
// k-dim pair packing: within every 8-group along K, store order
//   (k0,k0+4),(k0+1,k0+5),(k0+2,k0+6),(k0+3,k0+7)
// so each mma.m16n8k8 fragment (needs k+c and k+c+4) is an adjacent float2.
// ---------------------------------------------------------------------------

#define MROWS 131072L
#define CDIM  256
#define QKVN  768
#define NWIN  512
#define NHEAD 8
#define HDIM  32

static const long OUT_ELEMS  = MROWS * CDIM;                    // 33,554,432
static const long ATTN_ELEMS = (long)NWIN * NHEAD * 256 * 256;  // 268,435,456

__device__ float g_qkv[MROWS * QKVN];   // qkv output (natural layout)
__device__ float g_o  [MROWS * CDIM];   // attention output (k-pair-packed, tf32)
__device__ float g_xt [MROWS * CDIM];   // x (k-pair-packed, tf32)
__device__ float g_wq [CDIM * QKVN];    // qkv_w packed [kt][ks][c][N][2], tf32
__device__ float g_wp [CDIM * CDIM];    // proj_w packed likewise

// ---- helpers ----
__device__ __forceinline__ float cvt_tf32(float x) {
    uint32_t r; asm("cvt.rna.tf32.f32 %0, %1;" : "=r"(r) : "f"(x));
    return __uint_as_float(r);
}
__device__ __forceinline__ void cp_async16(uint32_t dst, const void* src) {
    asm volatile("cp.async.cg.shared.global [%0], [%1], 16;" :: "r"(dst), "l"(src));
}
__device__ __forceinline__ void mma_tf32(float* d, const uint32_t* a,
                                         uint32_t b0, uint32_t b1) {
    asm volatile(
        "mma.sync.aligned.m16n8k8.row.col.f32.tf32.tf32.f32 "
        "{%0,%1,%2,%3}, {%4,%5,%6,%7}, {%8,%9}, {%0,%1,%2,%3};"
        : "+f"(d[0]), "+f"(d[1]), "+f"(d[2]), "+f"(d[3])
        : "r"(a[0]), "r"(a[1]), "r"(a[2]), "r"(a[3]), "r"(b0), "r"(b1));
}

// ---------------------------------------------------------------------------
// x / A-side prep: tf32 round + permute each 8-group along the row to
// (0,4),(1,5),(2,6),(3,7).  One thread per 8-float group.
// ---------------------------------------------------------------------------
__global__ void cvt_perm(const float* __restrict__ in, float* __restrict__ out,
                         long n8)
{
    long i = (long)blockIdx.x * blockDim.x + threadIdx.x;
    long stride = (long)gridDim.x * blockDim.x;
    for (; i < n8; i += stride) {
        const float4* s = (const float4*)in + i * 2;
        float4 u = s[0], v = s[1];
        float4 o0, o1;
        o0.x = cvt_tf32(u.x); o0.y = cvt_tf32(v.x);   // (0,4)
        o0.z = cvt_tf32(u.y); o0.w = cvt_tf32(v.y);   // (1,5)
        o1.x = cvt_tf32(u.z); o1.y = cvt_tf32(v.z);   // (2,6)
        o1.z = cvt_tf32(u.w); o1.w = cvt_tf32(v.w);   // (3,7)
        float4* d = (float4*)out + i * 2;
        d[0] = o0; d[1] = o1;
    }
}

// ---------------------------------------------------------------------------
// Weight prep: B[k][n] (natural [K][N]) -> packed [kt][ks][c][N][2], tf32.
//   k = kt*32 + ks*8 + j;  j<4 -> (c=j, slot=0), j>=4 -> (c=j-4, slot=1)
// ---------------------------------------------------------------------------
__global__ void pack_weights(const float* __restrict__ in, float* __restrict__ out,
                             int K, int N)
{
    long total = (long)K * N;
    long idx = (long)blockIdx.x * blockDim.x + threadIdx.x;
    long stride = (long)gridDim.x * blockDim.x;
    for (; idx < total; idx += stride) {
        int k = (int)(idx / N), n = (int)(idx % N);
        int kt = k >> 5, kk = k & 31, ks = kk >> 3, j = kk & 7;
        int c = j & 3, slot = j >> 2;
        long off = ((((long)kt * 4 + ks) * 4 + c) * N + n) * 2 + slot;
        out[off] = cvt_tf32(in[idx]);
    }
}

// ---------------------------------------------------------------------------
// tf32 tensor-core GEMM with pair-packed operands.
//   A: [M][256] k-pair-packed rows.  Bp: packed [kt][ks][c][N][2].
//   Block 128x128, K-tile 32, 8 warps (4M x 2N), warp tile 32x64.
//   smem: As [2][128][36] (pairs at ks*8+2c), Bs [2][16][264] ((ks,c) rows).
// ---------------------------------------------------------------------------
#define SA 36
#define SBR 264                               // floats per (ks,c) smem row
#define GEMM_SMEM ((2*128*SA + 2*16*SBR) * 4) // 70,656 bytes

__global__ __launch_bounds__(256, 2)
void sgemm_tf32(const float* __restrict__ A, const float* __restrict__ Bp,
                const float* __restrict__ bias, float* __restrict__ C, int N)
{
    extern __shared__ float smem[];
    float* As = smem;                  // 2 * 128*36
    float* Bs = smem + 2 * 128 * SA;   // 2 * 16*264

    const int tid  = threadIdx.x;
    const int bm   = blockIdx.y * 128;
    const int bn   = blockIdx.x * 128;
    const int lane = tid & 31;
    const int warp = tid >> 5;
    const int warpM = warp >> 1;
    const int warpN = warp & 1;
    const int g = lane >> 2, c = lane & 3;

    // A loader: row am (0..127), 16-float half ak
    const int am  = tid >> 1;
    const int ak  = (tid & 1) * 16;
    const float* Ag = A + (long)(bm + am) * 256 + ak;
    // B loader: (ks,c) row r = tid>>4 (0..15), 16 chunk-threads per row, 4 chunks each
    const int br  = tid >> 4;
    const int bq0 = tid & 15;
    const float* Bg = Bp + (long)br * 2 * N + (long)bn * 2;

    const uint32_t as_base = (uint32_t)__cvta_generic_to_shared(As);
    const uint32_t bs_base = (uint32_t)__cvta_generic_to_shared(Bs);

    float d[2][8][4];
#pragma unroll
    for (int mm = 0; mm < 2; mm++)
#pragma unroll
        for (int nm = 0; nm < 8; nm++)
#pragma unroll
            for (int q = 0; q < 4; q++) d[mm][nm][q] = 0.f;

#define ISSUE(kt) do {                                                           \
        int buf_ = (kt) & 1;                                                     \
        uint32_t ad_ = as_base + (uint32_t)(buf_ * 128 * SA + am * SA + ak) * 4; \
        const float* asrc_ = Ag + (kt) * 32;                                     \
        _Pragma("unroll")                                                        \
        for (int q = 0; q < 4; q++) cp_async16(ad_ + q * 16, asrc_ + q * 4);     \
        const float* bsrc_ = Bg + (long)(kt) * 32 * N;                           \
        uint32_t bd_ = bs_base + (uint32_t)(buf_ * 16 * SBR + br * SBR) * 4;     \
        _Pragma("unroll")                                                        \
        for (int q = 0; q < 4; q++) {                                            \
            int ci_ = bq0 + 16 * q;                                              \
            cp_async16(bd_ + (uint32_t)ci_ * 16, bsrc_ + ci_ * 4);               \
        }                                                                        \
        asm volatile("cp.async.commit_group;");                                  \
    } while (0)

    ISSUE(0);
    ISSUE(1);

    for (int kt = 0; kt < 8; kt++) {
        if (kt < 6) asm volatile("cp.async.wait_group 1;");
        else        asm volatile("cp.async.wait_group 0;");
        __syncthreads();

        const float* Ab = As + (kt & 1) * 128 * SA;
        const float* Bb = Bs + (kt & 1) * 16 * SBR;

#pragma unroll
        for (int ks = 0; ks < 4; ks++) {
            uint32_t a[2][4];
#pragma unroll
            for (int mm = 0; mm < 2; mm++) {
                const float* p = Ab + (warpM * 32 + mm * 16 + g) * SA + ks * 8 + 2 * c;
                float2 u0 = *(const float2*)p;              // (a0, a2)
                float2 u1 = *(const float2*)(p + 8 * SA);   // (a1, a3)
                a[mm][0] = __float_as_uint(u0.x);
                a[mm][1] = __float_as_uint(u1.x);
                a[mm][2] = __float_as_uint(u0.y);
                a[mm][3] = __float_as_uint(u1.y);
            }
            const float* brow = Bb + (ks * 4 + c) * SBR;
#pragma unroll
            for (int nm = 0; nm < 8; nm++) {
                float2 v = *(const float2*)(brow + (warpN * 64 + nm * 8 + g) * 2);
                uint32_t b0 = __float_as_uint(v.x);
                uint32_t b1 = __float_as_uint(v.y);
                mma_tf32(d[0][nm], a[0], b0, b1);
                mma_tf32(d[1][nm], a[1], b0, b1);
            }
        }
        __syncthreads();
        if (kt + 2 < 8) ISSUE(kt + 2);
    }
#undef ISSUE

#pragma unroll
    for (int nm = 0; nm < 8; nm++) {
        const int col = bn + warpN * 64 + nm * 8 + (lane & 3) * 2;
        const float2 bv = *(const float2*)(bias + col);
#pragma unroll
        for (int mm = 0; mm < 2; mm++) {
            const int r0 = bm + warpM * 32 + mm * 16 + (lane >> 2);
            float2 v0 = { d[mm][nm][0] + bv.x, d[mm][nm][1] + bv.y };
            float2 v1 = { d[mm][nm][2] + bv.x, d[mm][nm][3] + bv.y };
            *(float2*)(C + (long)r0 * N + col)       = v0;
            *(float2*)(C + (long)(r0 + 8) * N + col) = v1;
        }
    }
}

// ---------------------------------------------------------------------------
// Windowed attention on tensor cores (R13, unchanged except o_out stores in
// k-pair-packed channel order for the proj GEMM).
// ---------------------------------------------------------------------------
#define AT_KT 0
#define AT_VS 8448               // 32*264
#define AT_SS 18688              // + 256*40
#define AT_QS 27136              // + 32*264
#define AT_FLOATS 28288          // + 32*36
#define AT_BYTES (AT_FLOATS * 4) // 113,152

__global__ __launch_bounds__(256, 2)
void attn_tc(const float* __restrict__ qkv, float* __restrict__ o_out,
             float* __restrict__ attn)
{
    extern __shared__ float sm[];
    float* KT = sm + AT_KT;
    float* VS = sm + AT_VS;
    float* SS = sm + AT_SS;
    float* QS = sm + AT_QS;

    const int bid = blockIdx.x;
    const int win = bid >> 3, h = bid & 7;
    const int b = win >> 8, win_y = (win >> 4) & 15, win_x = win & 15;
    const int tid  = threadIdx.x;
    const int lane = tid & 31, w = tid >> 5;
    const int g = lane >> 2, c = lane & 3;

    const long tok_base  = (long)b * 65536 + (long)(win_y * 16) * 256 + win_x * 16;
    const long attn_base = ((long)win * NHEAD + h) * 65536;
    const float scale = 0.17677669529663687f;   // 32^-0.5

    {
        const int t = tid;
        const long gtok = tok_base + (long)(t >> 4) * 256 + (t & 15);
        const float4* src = (const float4*)(qkv + gtok * QKVN + h * HDIM);
#pragma unroll
        for (int d4 = 0; d4 < 8; d4++) {
            float4 kv = src[64 + d4];
            float4 vv = src[128 + d4];
            KT[(d4 * 4 + 0) * 264 + t] = cvt_tf32(kv.x);
            KT[(d4 * 4 + 1) * 264 + t] = cvt_tf32(kv.y);
            KT[(d4 * 4 + 2) * 264 + t] = cvt_tf32(kv.z);
            KT[(d4 * 4 + 3) * 264 + t] = cvt_tf32(kv.w);
            vv.x = cvt_tf32(vv.x); vv.y = cvt_tf32(vv.y);
            vv.z = cvt_tf32(vv.z); vv.w = cvt_tf32(vv.w);
            *(float4*)(VS + t * 40 + d4 * 4) = vv;
        }
    }

    for (int qc = 0; qc < 8; qc++) {
        {
            const int row = tid >> 3;
            const int dc  = (tid & 7) * 4;
            const int rw  = qc * 32 + row;
            const long gtok = tok_base + (long)(rw >> 4) * 256 + (rw & 15);
            float4 qv = *(const float4*)(qkv + gtok * QKVN + h * HDIM + dc);
            qv.x = cvt_tf32(qv.x); qv.y = cvt_tf32(qv.y);
            qv.z = cvt_tf32(qv.z); qv.w = cvt_tf32(qv.w);
            *(float4*)(QS + row * 36 + dc) = qv;
        }
        __syncthreads();                               // (1) Q/K/V ready

        float d[2][4][4];
#pragma unroll
        for (int mm = 0; mm < 2; mm++)
#pragma unroll
            for (int nm = 0; nm < 4; nm++)
#pragma unroll
                for (int q = 0; q < 4; q++) d[mm][nm][q] = 0.f;

#pragma unroll
        for (int ks = 0; ks < 4; ks++) {
            const int kof = ks * 8;
            uint32_t a[2][4];
#pragma unroll
            for (int mm = 0; mm < 2; mm++) {
                const float* p = QS + (mm * 16 + g) * 36 + kof + c;
                a[mm][0] = __float_as_uint(p[0]);
                a[mm][1] = __float_as_uint(p[8 * 36]);
                a[mm][2] = __float_as_uint(p[4]);
                a[mm][3] = __float_as_uint(p[8 * 36 + 4]);
            }
#pragma unroll
            for (int nm = 0; nm < 4; nm++) {
                const float* p = KT + (kof + c) * 264 + w * 32 + nm * 8 + g;
                uint32_t b0 = __float_as_uint(p[0]);
                uint32_t b1 = __float_as_uint(p[4 * 264]);
                mma_tf32(d[0][nm], a[0], b0, b1);
                mma_tf32(d[1][nm], a[1], b0, b1);
            }
        }
#pragma unroll
        for (int mm = 0; mm < 2; mm++)
#pragma unroll
            for (int nm = 0; nm < 4; nm++) {
                float* p = SS + (mm * 16 + g) * 264 + w * 32 + nm * 8 + 2 * c;
                *(float2*)p             = make_float2(d[mm][nm][0], d[mm][nm][1]);
                *(float2*)(p + 8 * 264) = make_float2(d[mm][nm][2], d[mm][nm][3]);
            }
        __syncthreads();                               // (2) S complete

#pragma unroll
        for (int i = 0; i < 4; i++) {
            const int row = w * 4 + i;
            float sv[8];
#pragma unroll
            for (int jj = 0; jj < 8; jj++)
                sv[jj] = SS[row * 264 + jj * 32 + lane] * scale;
            float m = sv[0];
#pragma unroll
            for (int jj = 1; jj < 8; jj++) m = fmaxf(m, sv[jj]);
#pragma unroll
            for (int off = 16; off > 0; off >>= 1)
                m = fmaxf(m, __shfl_xor_sync(0xffffffffu, m, off));
            float l = 0.f;
#pragma unroll
            for (int jj = 0; jj < 8; jj++) { sv[jj] = __expf(sv[jj] - m); l += sv[jj]; }
#pragma unroll
            for (int off = 16; off > 0; off >>= 1)
                l += __shfl_xor_sync(0xffffffffu, l, off);
            const float inv = 1.f / l;
            const long arow = attn_base + (long)(qc * 32 + row) * 256;
#pragma unroll
            for (int jj = 0; jj < 8; jj++) {
                float p = sv[jj] * inv;
                if (attn) __stcs(attn + arow + jj * 32 + lane, p);
                SS[row * 264 + jj * 32 + lane] = cvt_tf32(p);
            }
        }
        __syncthreads();                               // (3) P ready

        float e[2][4][4];
#pragma unroll
        for (int mm = 0; mm < 2; mm++)
#pragma unroll
            for (int nm = 0; nm < 4; nm++)
#pragma unroll
                for (int q = 0; q < 4; q++) e[mm][nm][q] = 0.f;

#pragma unroll
        for (int ks = 0; ks < 4; ks++) {
            const int kof = w * 32 + ks * 8;
            uint32_t a[2][4];
#pragma unroll
            for (int mm = 0; mm < 2; mm++) {
                const float* p = SS + (mm * 16 + g) * 264 + kof + c;
                a[mm][0] = __float_as_uint(p[0]);
                a[mm][1] = __float_as_uint(p[8 * 264]);
                a[mm][2] = __float_as_uint(p[4]);
                a[mm][3] = __float_as_uint(p[8 * 264 + 4]);
            }
#pragma unroll
            for (int nm = 0; nm < 4; nm++) {
                const float* p = VS + (kof + c) * 40 + nm * 8 + g;
                uint32_t b0 = __float_as_uint(p[0]);
                uint32_t b1 = __float_as_uint(p[4 * 40]);
                mma_tf32(e[0][nm], a[0], b0, b1);
                mma_tf32(e[1][nm], a[1], b0, b1);
            }
        }
        __syncthreads();                               // (4) P reads done

        // partials -> SS as part[w][32][33] (stride 33 odd: scalar stores only)
#pragma unroll
        for (int mm = 0; mm < 2; mm++)
#pragma unroll
            for (int nm = 0; nm < 4; nm++) {
                const int base = w * 1056 + (mm * 16 + g) * 33 + nm * 8 + 2 * c;
                SS[base]              = e[mm][nm][0];
                SS[base + 1]          = e[mm][nm][1];
                SS[base + 8 * 33]     = e[mm][nm][2];
                SS[base + 8 * 33 + 1] = e[mm][nm][3];
            }
        __syncthreads();                               // (5) partials staged

        {
            const int dd = tid & 31;
            const int r0 = (tid >> 5) * 4;
            // k-pair-packed channel position for proj GEMM A operand
            const int jp = dd & 7;
            const int pos = (jp < 4) ? (2 * jp) : (2 * (jp - 4) + 1);
            const int chp = h * HDIM + (dd & ~7) + pos;
#pragma unroll
            for (int i = 0; i < 4; i++) {
                const int r = r0 + i;
                float acc = 0.f;
#pragma unroll
                for (int wp = 0; wp < 8; wp++)
                    acc += SS[wp * 1056 + r * 33 + dd];
                const int rw = qc * 32 + r;
                const long gtok = tok_base + (long)(rw >> 4) * 256 + (rw & 15);
                o_out[gtok * CDIM + chp] = cvt_tf32(acc);
            }
        }
        __syncthreads();                               // (6) SS/QS free
    }
}

// ---------------------------------------------------------------------------
extern "C" void kernel_launch(void* const* d_in, const int* in_sizes, int n_in,
                              void* d_out, int out_size)
{
    (void)in_sizes; (void)n_in;
    const float* x      = (const float*)d_in[0];
    const float* qkv_w  = (const float*)d_in[1];
    const float* qkv_b  = (const float*)d_in[2];
    const float* proj_w = (const float*)d_in[3];
    const float* proj_b = (const float*)d_in[4];

    float *qkv_buf, *o_buf, *xt, *wq, *wp;
    cudaGetSymbolAddress((void**)&qkv_buf, g_qkv);
    cudaGetSymbolAddress((void**)&o_buf,   g_o);
    cudaGetSymbolAddress((void**)&xt,      g_xt);
    cudaGetSymbolAddress((void**)&wq,      g_wq);
    cudaGetSymbolAddress((void**)&wp,      g_wp);

    float* out_ptr  = (float*)d_out;
    float* attn_ptr = nullptr;
    long osz = (long)out_size;
    if (osz >= OUT_ELEMS + ATTN_ELEMS) {
        out_ptr  = (float*)d_out;
        attn_ptr = (float*)d_out + OUT_ELEMS;
    } else if (osz == ATTN_ELEMS) {
        attn_ptr = (float*)d_out;
        out_ptr  = qkv_buf;
    }

    // 0) operand prep: x -> k-pair-packed tf32; weights -> packed tiles
    cvt_perm<<<4096, 256>>>(x, xt, OUT_ELEMS / 8);
    pack_weights<<<192, 256>>>(qkv_w,  wq, CDIM, QKVN);
    pack_weights<<<64,  256>>>(proj_w, wp, CDIM, CDIM);

    // 1) QKV projection (tf32 mma.sync, packed operands)
    cudaFuncSetAttribute(sgemm_tf32, cudaFuncAttributeMaxDynamicSharedMemorySize, GEMM_SMEM);
    sgemm_tf32<<<dim3(QKVN / 128, (int)(MROWS / 128)), 256, GEMM_SMEM>>>(
        xt, wq, qkv_b, qkv_buf, QKVN);

    // 2) Windowed attention (tf32 mma.sync)
    cudaFuncSetAttribute(attn_tc, cudaFuncAttributeMaxDynamicSharedMemorySize, AT_BYTES);
    attn_tc<<<NWIN * NHEAD, 256, AT_BYTES>>>(qkv_buf, o_buf, attn_ptr);

    // 3) Output projection (tf32 mma.sync, packed operands)
    sgemm_tf32<<<dim3(CDIM / 128, (int)(MROWS / 128)), 256, GEMM_SMEM>>>(
        o_buf, wp, proj_b, out_ptr, CDIM);
}

// round 15
// speedup vs baseline: 1.9061x; 1.9061x over previous
#include <cuda_runtime.h>
#include <cuda_fp16.h>
#include <math.h>
#include <stdint.h>

// ---------------------------------------------------------------------------
// LocalSparseAttention — fp16 ldmatrix/mma GEMMs + tf32 mma attention
//   B=2, N=65536 (256x256), C=256, window=16 (256 tok/window), heads=8, hd=32
// ---------------------------------------------------------------------------

#define MROWS 131072L
#define CDIM  256
#define QKVN  768
#define NWIN  512
#define NHEAD 8
#define HDIM  32

static const long OUT_ELEMS  = MROWS * CDIM;                    // 33,554,432
static const long ATTN_ELEMS = (long)NWIN * NHEAD * 256 * 256;  // 268,435,456

__device__ float  g_qkv[MROWS * QKVN];   // qkv output (fp32, natural)
__device__ __half g_oh [MROWS * CDIM];   // attention output (half, natural)
__device__ __half g_xh [MROWS * CDIM];   // x as half
__device__ __half g_wq [QKVN * CDIM];    // qkv_w^T  [768][256] half
__device__ __half g_wp [CDIM * CDIM];    // proj_w^T [256][256] half

// ---- helpers ----
__device__ __forceinline__ float cvt_tf32(float x) {
    uint32_t r; asm("cvt.rna.tf32.f32 %0, %1;" : "=r"(r) : "f"(x));
    return __uint_as_float(r);
}
__device__ __forceinline__ void cp_async16(uint32_t dst, const void* src) {
    asm volatile("cp.async.cg.shared.global [%0], [%1], 16;" :: "r"(dst), "l"(src));
}
__device__ __forceinline__ void mma_tf32(float* d, const uint32_t* a,
                                         uint32_t b0, uint32_t b1) {
    asm volatile(
        "mma.sync.aligned.m16n8k8.row.col.f32.tf32.tf32.f32 "
        "{%0,%1,%2,%3}, {%4,%5,%6,%7}, {%8,%9}, {%0,%1,%2,%3};"
        : "+f"(d[0]), "+f"(d[1]), "+f"(d[2]), "+f"(d[3])
        : "r"(a[0]), "r"(a[1]), "r"(a[2]), "r"(a[3]), "r"(b0), "r"(b1));
}
__device__ __forceinline__ void mma_f16(float* d, const uint32_t* a,
                                        uint32_t b0, uint32_t b1) {
    asm volatile(
        "mma.sync.aligned.m16n8k16.row.col.f32.f16.f16.f32 "
        "{%0,%1,%2,%3}, {%4,%5,%6,%7}, {%8,%9}, {%0,%1,%2,%3};"
        : "+f"(d[0]), "+f"(d[1]), "+f"(d[2]), "+f"(d[3])
        : "r"(a[0]), "r"(a[1]), "r"(a[2]), "r"(a[3]), "r"(b0), "r"(b1));
}
__device__ __forceinline__ void ldmatrix_x4(uint32_t* r, uint32_t addr) {
    asm volatile("ldmatrix.sync.aligned.m8n8.x4.shared.b16 {%0,%1,%2,%3}, [%4];"
                 : "=r"(r[0]), "=r"(r[1]), "=r"(r[2]), "=r"(r[3]) : "r"(addr));
}

// ---------------------------------------------------------------------------
// Prep: x (fp32) -> half
// ---------------------------------------------------------------------------
__global__ void cvt_f16(const float* __restrict__ in, __half* __restrict__ out,
                        long n4)
{
    long i = (long)blockIdx.x * blockDim.x + threadIdx.x;
    long stride = (long)gridDim.x * blockDim.x;
    for (; i < n4; i += stride) {
        float4 v = ((const float4*)in)[i];
        __half2 h0 = __floats2half2_rn(v.x, v.y);
        __half2 h1 = __floats2half2_rn(v.z, v.w);
        ((__half2*)out)[2 * i]     = h0;
        ((__half2*)out)[2 * i + 1] = h1;
    }
}

// Prep: W[k][n] (fp32, [K][N]) -> WT[n][k] (half)
__global__ void transpose_cvt_h(const float* __restrict__ in,
                                __half* __restrict__ out, int K, int N)
{
    __shared__ float t[32][33];
    const int bx = blockIdx.x * 32;   // n
    const int by = blockIdx.y * 32;   // k
    const int x = threadIdx.x, y = threadIdx.y;
    for (int i = y; i < 32; i += 8)
        t[i][x] = in[(long)(by + i) * N + bx + x];
    __syncthreads();
    for (int i = y; i < 32; i += 8)
        out[(long)(bx + i) * K + by + x] = __float2half_rn(t[x][i]);
}

// ---------------------------------------------------------------------------
// fp16 tensor-core GEMM: C[M,N] = A[M,256] @ WT^T + bias   (fp32 out)
//   A [M][256] half row-major; BT [N][256] half row-major (= W^T).
//   Block 128x128, K-tile 32, 8 warps (4M x 2N), warp tile 32x64.
//   smem/stage: A 128x64B (8KB) + B 128x64B (8KB); 2 stages = 32KB.
//   16B-chunk swizzle q ^= (row>>1)&3  -> ldmatrix phases conflict-free.
// ---------------------------------------------------------------------------
#define HG_SMEM 32768

__global__ __launch_bounds__(256, 2)
void hgemm(const __half* __restrict__ A, const __half* __restrict__ BT,
           const float* __restrict__ bias, float* __restrict__ C, int N)
{
    extern __shared__ char smem[];
    const uint32_t sb = (uint32_t)__cvta_generic_to_shared(smem);
    const int tid = threadIdx.x;
    const int bm = blockIdx.y * 128, bn = blockIdx.x * 128;
    const int lane = tid & 31, warp = tid >> 5;
    const int warpM = warp >> 1, warpN = warp & 1;

    // loader: thread t -> row t>>1, chunk pair (t&1)*2
    const int lrow = tid >> 1;
    const int lq   = (tid & 1) * 2;
    const int lxr  = (lrow >> 1) & 3;
    const uint32_t l_off = (uint32_t)lrow * 64;
    const __half* Ag = A  + (long)(bm + lrow) * 256;
    const __half* Bg = BT + (long)(bn + lrow) * 256;

    // fragment lane params (constant per thread)
    const int ahi = lane >> 4;                        // A k-chunk hi bit
    const int bhi = (lane >> 3) & 1;                  // B k-chunk hi bit
    int arow0 = warpM * 32 + (lane & 7) + ((lane >> 3) & 1) * 8;
    uint32_t aoff[2], axr[2];
    aoff[0] = (uint32_t)arow0 * 64;          axr[0] = (arow0 >> 1) & 3;
    aoff[1] = (uint32_t)(arow0 + 16) * 64;   axr[1] = ((arow0 + 16) >> 1) & 3;
    uint32_t boff[4], bxr[4];
#pragma unroll
    for (int np = 0; np < 4; np++) {
        int nrow = warpN * 64 + np * 16 + (lane & 7) + (lane >> 4) * 8;
        boff[np] = (uint32_t)nrow * 64;
        bxr[np]  = (nrow >> 1) & 3;
    }

    float d[2][8][4];
#pragma unroll
    for (int mm = 0; mm < 2; mm++)
#pragma unroll
        for (int nm = 0; nm < 8; nm++)
#pragma unroll
            for (int q = 0; q < 4; q++) d[mm][nm][q] = 0.f;

#define ISSUE(kt) do {                                                        \
        uint32_t st_ = sb + ((kt) & 1) * 16384;                               \
        const __half* as_ = Ag + (kt) * 32;                                   \
        cp_async16(st_ + l_off + (uint32_t)((lq ^ lxr) << 4),       as_ + lq * 8);      \
        cp_async16(st_ + l_off + (uint32_t)(((lq + 1) ^ lxr) << 4), as_ + lq * 8 + 8);  \
        const __half* bs_ = Bg + (kt) * 32;                                   \
        cp_async16(st_ + 8192 + l_off + (uint32_t)((lq ^ lxr) << 4),       bs_ + lq * 8);     \
        cp_async16(st_ + 8192 + l_off + (uint32_t)(((lq + 1) ^ lxr) << 4), bs_ + lq * 8 + 8); \
        asm volatile("cp.async.commit_group;");                               \
    } while (0)

    ISSUE(0);
    ISSUE(1);

    for (int kt = 0; kt < 8; kt++) {
        if (kt < 6) asm volatile("cp.async.wait_group 1;");
        else        asm volatile("cp.async.wait_group 0;");
        __syncthreads();

        const uint32_t st = sb + (kt & 1) * 16384;
#pragma unroll
        for (int s = 0; s < 2; s++) {
            uint32_t a[2][4];
#pragma unroll
            for (int mm = 0; mm < 2; mm++)
                ldmatrix_x4(a[mm],
                    st + aoff[mm] + (uint32_t)(((2 * s + ahi) ^ axr[mm]) << 4));
#pragma unroll
            for (int np = 0; np < 4; np++) {
                uint32_t b[4];
                ldmatrix_x4(b,
                    st + 8192 + boff[np] + (uint32_t)(((2 * s + bhi) ^ bxr[np]) << 4));
                mma_f16(d[0][2 * np],     a[0], b[0], b[1]);
                mma_f16(d[1][2 * np],     a[1], b[0], b[1]);
                mma_f16(d[0][2 * np + 1], a[0], b[2], b[3]);
                mma_f16(d[1][2 * np + 1], a[1], b[2], b[3]);
            }
        }
        __syncthreads();
        if (kt + 2 < 8) ISSUE(kt + 2);
    }
#undef ISSUE

    // epilogue: bias + fp32 store (same frag layout as m16n8k8)
    const int g = lane >> 2, c = lane & 3;
#pragma unroll
    for (int nm = 0; nm < 8; nm++) {
        const int col = bn + warpN * 64 + nm * 8 + c * 2;
        const float2 bv = *(const float2*)(bias + col);
#pragma unroll
        for (int mm = 0; mm < 2; mm++) {
            const int r0 = bm + warpM * 32 + mm * 16 + g;
            float2 v0 = { d[mm][nm][0] + bv.x, d[mm][nm][1] + bv.y };
            float2 v1 = { d[mm][nm][2] + bv.x, d[mm][nm][3] + bv.y };
            *(float2*)(C + (long)r0 * N + col)       = v0;
            *(float2*)(C + (long)(r0 + 8) * N + col) = v1;
        }
    }
}

// ---------------------------------------------------------------------------
// Windowed attention on tensor cores (R13 tf32 version; epilogue stores half)
// ---------------------------------------------------------------------------
#define AT_KT 0
#define AT_VS 8448               // 32*264
#define AT_SS 18688              // + 256*40
#define AT_QS 27136              // + 32*264
#define AT_FLOATS 28288          // + 32*36
#define AT_BYTES (AT_FLOATS * 4) // 113,152

__global__ __launch_bounds__(256, 2)
void attn_tc(const float* __restrict__ qkv, __half* __restrict__ o_out,
             float* __restrict__ attn)
{
    extern __shared__ float sm[];
    float* KT = sm + AT_KT;
    float* VS = sm + AT_VS;
    float* SS = sm + AT_SS;
    float* QS = sm + AT_QS;

    const int bid = blockIdx.x;
    const int win = bid >> 3, h = bid & 7;
    const int b = win >> 8, win_y = (win >> 4) & 15, win_x = win & 15;
    const int tid  = threadIdx.x;
    const int lane = tid & 31, w = tid >> 5;
    const int g = lane >> 2, c = lane & 3;

    const long tok_base  = (long)b * 65536 + (long)(win_y * 16) * 256 + win_x * 16;
    const long attn_base = ((long)win * NHEAD + h) * 65536;
    const float scale = 0.17677669529663687f;   // 32^-0.5

    {
        const int t = tid;
        const long gtok = tok_base + (long)(t >> 4) * 256 + (t & 15);
        const float4* src = (const float4*)(qkv + gtok * QKVN + h * HDIM);
#pragma unroll
        for (int d4 = 0; d4 < 8; d4++) {
            float4 kv = src[64 + d4];
            float4 vv = src[128 + d4];
            KT[(d4 * 4 + 0) * 264 + t] = cvt_tf32(kv.x);
            KT[(d4 * 4 + 1) * 264 + t] = cvt_tf32(kv.y);
            KT[(d4 * 4 + 2) * 264 + t] = cvt_tf32(kv.z);
            KT[(d4 * 4 + 3) * 264 + t] = cvt_tf32(kv.w);
            vv.x = cvt_tf32(vv.x); vv.y = cvt_tf32(vv.y);
            vv.z = cvt_tf32(vv.z); vv.w = cvt_tf32(vv.w);
            *(float4*)(VS + t * 40 + d4 * 4) = vv;
        }
    }

    for (int qc = 0; qc < 8; qc++) {
        {
            const int row = tid >> 3;
            const int dc  = (tid & 7) * 4;
            const int rw  = qc * 32 + row;
            const long gtok = tok_base + (long)(rw >> 4) * 256 + (rw & 15);
            float4 qv = *(const float4*)(qkv + gtok * QKVN + h * HDIM + dc);
            qv.x = cvt_tf32(qv.x); qv.y = cvt_tf32(qv.y);
            qv.z = cvt_tf32(qv.z); qv.w = cvt_tf32(qv.w);
            *(float4*)(QS + row * 36 + dc) = qv;
        }
        __syncthreads();                               // (1) Q/K/V ready

        float d[2][4][4];
#pragma unroll
        for (int mm = 0; mm < 2; mm++)
#pragma unroll
            for (int nm = 0; nm < 4; nm++)
#pragma unroll
                for (int q = 0; q < 4; q++) d[mm][nm][q] = 0.f;

#pragma unroll
        for (int ks = 0; ks < 4; ks++) {
            const int kof = ks * 8;
            uint32_t a[2][4];
#pragma unroll
            for (int mm = 0; mm < 2; mm++) {
                const float* p = QS + (mm * 16 + g) * 36 + kof + c;
                a[mm][0] = __float_as_uint(p[0]);
                a[mm][1] = __float_as_uint(p[8 * 36]);
                a[mm][2] = __float_as_uint(p[4]);
                a[mm][3] = __float_as_uint(p[8 * 36 + 4]);
            }
#pragma unroll
            for (int nm = 0; nm < 4; nm++) {
                const float* p = KT + (kof + c) * 264 + w * 32 + nm * 8 + g;
                uint32_t b0 = __float_as_uint(p[0]);
                uint32_t b1 = __float_as_uint(p[4 * 264]);
                mma_tf32(d[0][nm], a[0], b0, b1);
                mma_tf32(d[1][nm], a[1], b0, b1);
            }
        }
#pragma unroll
        for (int mm = 0; mm < 2; mm++)
#pragma unroll
            for (int nm = 0; nm < 4; nm++) {
                float* p = SS + (mm * 16 + g) * 264 + w * 32 + nm * 8 + 2 * c;
                *(float2*)p             = make_float2(d[mm][nm][0], d[mm][nm][1]);
                *(float2*)(p + 8 * 264) = make_float2(d[mm][nm][2], d[mm][nm][3]);
            }
        __syncthreads();                               // (2) S complete

#pragma unroll
        for (int i = 0; i < 4; i++) {
            const int row = w * 4 + i;
            float sv[8];
#pragma unroll
            for (int jj = 0; jj < 8; jj++)
                sv[jj] = SS[row * 264 + jj * 32 + lane] * scale;
            float m = sv[0];
#pragma unroll
            for (int jj = 1; jj < 8; jj++) m = fmaxf(m, sv[jj]);
#pragma unroll
            for (int off = 16; off > 0; off >>= 1)
                m = fmaxf(m, __shfl_xor_sync(0xffffffffu, m, off));
            float l = 0.f;
#pragma unroll
            for (int jj = 0; jj < 8; jj++) { sv[jj] = __expf(sv[jj] - m); l += sv[jj]; }
#pragma unroll
            for (int off = 16; off > 0; off >>= 1)
                l += __shfl_xor_sync(0xffffffffu, l, off);
            const float inv = 1.f / l;
            const long arow = attn_base + (long)(qc * 32 + row) * 256;
#pragma unroll
            for (int jj = 0; jj < 8; jj++) {
                float p = sv[jj] * inv;
                if (attn) __stcs(attn + arow + jj * 32 + lane, p);
                SS[row * 264 + jj * 32 + lane] = cvt_tf32(p);
            }
        }
        __syncthreads();                               // (3) P ready

        float e[2][4][4];
#pragma unroll
        for (int mm = 0; mm < 2; mm++)
#pragma unroll
            for (int nm = 0; nm < 4; nm++)
#pragma unroll
                for (int q = 0; q < 4; q++) e[mm][nm][q] = 0.f;

#pragma unroll
        for (int ks = 0; ks < 4; ks++) {
            const int kof = w * 32 + ks * 8;
            uint32_t a[2][4];
#pragma unroll
            for (int mm = 0; mm < 2; mm++) {
                const float* p = SS + (mm * 16 + g) * 264 + kof + c;
                a[mm][0] = __float_as_uint(p[0]);
                a[mm][1] = __float_as_uint(p[8 * 264]);
                a[mm][2] = __float_as_uint(p[4]);
                a[mm][3] = __float_as_uint(p[8 * 264 + 4]);
            }
#pragma unroll
            for (int nm = 0; nm < 4; nm++) {
                const float* p = VS + (kof + c) * 40 + nm * 8 + g;
                uint32_t b0 = __float_as_uint(p[0]);
                uint32_t b1 = __float_as_uint(p[4 * 40]);
                mma_tf32(e[0][nm], a[0], b0, b1);
                mma_tf32(e[1][nm], a[1], b0, b1);
            }
        }
        __syncthreads();                               // (4) P reads done

        // partials -> SS as part[w][32][33] (stride 33 odd: scalar stores only)
#pragma unroll
        for (int mm = 0; mm < 2; mm++)
#pragma unroll
            for (int nm = 0; nm < 4; nm++) {
                const int base = w * 1056 + (mm * 16 + g) * 33 + nm * 8 + 2 * c;
                SS[base]              = e[mm][nm][0];
                SS[base + 1]          = e[mm][nm][1];
                SS[base + 8 * 33]     = e[mm][nm][2];
                SS[base + 8 * 33 + 1] = e[mm][nm][3];
            }
        __syncthreads();                               // (5) partials staged

        {
            const int dd = tid & 31;
            const int r0 = (tid >> 5) * 4;
#pragma unroll
            for (int i = 0; i < 4; i++) {
                const int r = r0 + i;
                float acc = 0.f;
#pragma unroll
                for (int wp = 0; wp < 8; wp++)
                    acc += SS[wp * 1056 + r * 33 + dd];
                const int rw = qc * 32 + r;
                const long gtok = tok_base + (long)(rw >> 4) * 256 + (rw & 15);
                o_out[gtok * CDIM + h * HDIM + dd] = __float2half_rn(acc);
            }
        }
        __syncthreads();                               // (6) SS/QS free
    }
}

// ---------------------------------------------------------------------------
extern "C" void kernel_launch(void* const* d_in, const int* in_sizes, int n_in,
                              void* d_out, int out_size)
{
    (void)in_sizes; (void)n_in;
    const float* x      = (const float*)d_in[0];
    const float* qkv_w  = (const float*)d_in[1];
    const float* qkv_b  = (const float*)d_in[2];
    const float* proj_w = (const float*)d_in[3];
    const float* proj_b = (const float*)d_in[4];

    float*  qkv_buf; __half *oh, *xh, *wq, *wp;
    cudaGetSymbolAddress((void**)&qkv_buf, g_qkv);
    cudaGetSymbolAddress((void**)&oh,      g_oh);
    cudaGetSymbolAddress((void**)&xh,      g_xh);
    cudaGetSymbolAddress((void**)&wq,      g_wq);
    cudaGetSymbolAddress((void**)&wp,      g_wp);

    float* out_ptr  = (float*)d_out;
    float* attn_ptr = nullptr;
    long osz = (long)out_size;
    if (osz >= OUT_ELEMS + ATTN_ELEMS) {
        out_ptr  = (float*)d_out;
        attn_ptr = (float*)d_out + OUT_ELEMS;
    } else if (osz == ATTN_ELEMS) {
        attn_ptr = (float*)d_out;
        out_ptr  = qkv_buf;
    }

    // 0) prep: x -> half; weights -> [N][K] half
    cvt_f16<<<4096, 256>>>(x, xh, OUT_ELEMS / 4);
    transpose_cvt_h<<<dim3(QKVN / 32, CDIM / 32), dim3(32, 8)>>>(qkv_w,  wq, CDIM, QKVN);
    transpose_cvt_h<<<dim3(CDIM / 32, CDIM / 32), dim3(32, 8)>>>(proj_w, wp, CDIM, CDIM);

    // 1) QKV projection (fp16 ldmatrix/mma)
    cudaFuncSetAttribute(hgemm, cudaFuncAttributeMaxDynamicSharedMemorySize, HG_SMEM);
    hgemm<<<dim3(QKVN / 128, (int)(MROWS / 128)), 256, HG_SMEM>>>(
        xh, wq, qkv_b, qkv_buf, QKVN);

    // 2) Windowed attention (tf32 mma.sync; o emitted as half)
    cudaFuncSetAttribute(attn_tc, cudaFuncAttributeMaxDynamicSharedMemorySize, AT_BYTES);
    attn_tc<<<NWIN * NHEAD, 256, AT_BYTES>>>(qkv_buf, oh, attn_ptr);

    // 3) Output projection (fp16 ldmatrix/mma)
    hgemm<<<dim3(CDIM / 128, (int)(MROWS / 128)), 256, HG_SMEM>>>(
        oh, wp, proj_b, out_ptr, CDIM);
}

// round 16
// speedup vs baseline: 2.2997x; 1.2065x over previous
#include <cuda_runtime.h>
#include <cuda_fp16.h>
#include <math.h>
#include <stdint.h>

// ---------------------------------------------------------------------------
// LocalSparseAttention — fp16 ldmatrix/mma everywhere, fp32 softmax
//   B=2, N=65536 (256x256), C=256, window=16 (256 tok/window), heads=8, hd=32
// ---------------------------------------------------------------------------

#define MROWS 131072L
#define CDIM  256
#define QKVN  768
#define NWIN  512
#define NHEAD 8
#define HDIM  32

static const long OUT_ELEMS  = MROWS * CDIM;                    // 33,554,432
static const long ATTN_ELEMS = (long)NWIN * NHEAD * 256 * 256;  // 268,435,456

__device__ float  g_qkv[MROWS * QKVN];   // qkv output (fp32, natural)
__device__ __half g_oh [MROWS * CDIM];   // attention output (half, natural)
__device__ __half g_xh [MROWS * CDIM];   // x as half
__device__ __half g_wq [QKVN * CDIM];    // qkv_w^T  [768][256] half
__device__ __half g_wp [CDIM * CDIM];    // proj_w^T [256][256] half

// ---- helpers ----
__device__ __forceinline__ void cp_async16(uint32_t dst, const void* src) {
    asm volatile("cp.async.cg.shared.global [%0], [%1], 16;" :: "r"(dst), "l"(src));
}
__device__ __forceinline__ void mma_f16(float* d, const uint32_t* a,
                                        uint32_t b0, uint32_t b1) {
    asm volatile(
        "mma.sync.aligned.m16n8k16.row.col.f32.f16.f16.f32 "
        "{%0,%1,%2,%3}, {%4,%5,%6,%7}, {%8,%9}, {%0,%1,%2,%3};"
        : "+f"(d[0]), "+f"(d[1]), "+f"(d[2]), "+f"(d[3])
        : "r"(a[0]), "r"(a[1]), "r"(a[2]), "r"(a[3]), "r"(b0), "r"(b1));
}
__device__ __forceinline__ void ldmatrix_x4(uint32_t* r, uint32_t addr) {
    asm volatile("ldmatrix.sync.aligned.m8n8.x4.shared.b16 {%0,%1,%2,%3}, [%4];"
                 : "=r"(r[0]), "=r"(r[1]), "=r"(r[2]), "=r"(r[3]) : "r"(addr));
}
__device__ __forceinline__ uint32_t packh2(float a, float b) {
    __half2 h = __floats2half2_rn(a, b);
    return *(uint32_t*)&h;
}

// ---------------------------------------------------------------------------
// Prep kernels
// ---------------------------------------------------------------------------
__global__ void cvt_f16(const float* __restrict__ in, __half* __restrict__ out,
                        long n4)
{
    long i = (long)blockIdx.x * blockDim.x + threadIdx.x;
    long stride = (long)gridDim.x * blockDim.x;
    for (; i < n4; i += stride) {
        float4 v = ((const float4*)in)[i];
        __half2 h0 = __floats2half2_rn(v.x, v.y);
        __half2 h1 = __floats2half2_rn(v.z, v.w);
        ((__half2*)out)[2 * i]     = h0;
        ((__half2*)out)[2 * i + 1] = h1;
    }
}

__global__ void transpose_cvt_h(const float* __restrict__ in,
                                __half* __restrict__ out, int K, int N)
{
    __shared__ float t[32][33];
    const int bx = blockIdx.x * 32;   // n
    const int by = blockIdx.y * 32;   // k
    const int x = threadIdx.x, y = threadIdx.y;
    for (int i = y; i < 32; i += 8)
        t[i][x] = in[(long)(by + i) * N + bx + x];
    __syncthreads();
    for (int i = y; i < 32; i += 8)
        out[(long)(bx + i) * K + by + x] = __float2half_rn(t[x][i]);
}

// ---------------------------------------------------------------------------
// fp16 tensor-core GEMM (unchanged from R15 — measured 216us QKV)
// ---------------------------------------------------------------------------
#define HG_SMEM 32768

__global__ __launch_bounds__(256, 2)
void hgemm(const __half* __restrict__ A, const __half* __restrict__ BT,
           const float* __restrict__ bias, float* __restrict__ C, int N)
{
    extern __shared__ char smem[];
    const uint32_t sb = (uint32_t)__cvta_generic_to_shared(smem);
    const int tid = threadIdx.x;
    const int bm = blockIdx.y * 128, bn = blockIdx.x * 128;
    const int lane = tid & 31, warp = tid >> 5;
    const int warpM = warp >> 1, warpN = warp & 1;

    const int lrow = tid >> 1;
    const int lq   = (tid & 1) * 2;
    const int lxr  = (lrow >> 1) & 3;
    const uint32_t l_off = (uint32_t)lrow * 64;
    const __half* Ag = A  + (long)(bm + lrow) * 256;
    const __half* Bg = BT + (long)(bn + lrow) * 256;

    const int ahi = lane >> 4;
    const int bhi = (lane >> 3) & 1;
    int arow0 = warpM * 32 + (lane & 7) + ((lane >> 3) & 1) * 8;
    uint32_t aoff[2], axr[2];
    aoff[0] = (uint32_t)arow0 * 64;          axr[0] = (arow0 >> 1) & 3;
    aoff[1] = (uint32_t)(arow0 + 16) * 64;   axr[1] = ((arow0 + 16) >> 1) & 3;
    uint32_t boff[4], bxr[4];
#pragma unroll
    for (int np = 0; np < 4; np++) {
        int nrow = warpN * 64 + np * 16 + (lane & 7) + (lane >> 4) * 8;
        boff[np] = (uint32_t)nrow * 64;
        bxr[np]  = (nrow >> 1) & 3;
    }

    float d[2][8][4];
#pragma unroll
    for (int mm = 0; mm < 2; mm++)
#pragma unroll
        for (int nm = 0; nm < 8; nm++)
#pragma unroll
            for (int q = 0; q < 4; q++) d[mm][nm][q] = 0.f;

#define ISSUE(kt) do {                                                        \
        uint32_t st_ = sb + ((kt) & 1) * 16384;                               \
        const __half* as_ = Ag + (kt) * 32;                                   \
        cp_async16(st_ + l_off + (uint32_t)((lq ^ lxr) << 4),       as_ + lq * 8);      \
        cp_async16(st_ + l_off + (uint32_t)(((lq + 1) ^ lxr) << 4), as_ + lq * 8 + 8);  \
        const __half* bs_ = Bg + (kt) * 32;                                   \
        cp_async16(st_ + 8192 + l_off + (uint32_t)((lq ^ lxr) << 4),       bs_ + lq * 8);     \
        cp_async16(st_ + 8192 + l_off + (uint32_t)(((lq + 1) ^ lxr) << 4), bs_ + lq * 8 + 8); \
        asm volatile("cp.async.commit_group;");                               \
    } while (0)

    ISSUE(0);
    ISSUE(1);

    for (int kt = 0; kt < 8; kt++) {
        if (kt < 6) asm volatile("cp.async.wait_group 1;");
        else        asm volatile("cp.async.wait_group 0;");
        __syncthreads();

        const uint32_t st = sb + (kt & 1) * 16384;
#pragma unroll
        for (int s = 0; s < 2; s++) {
            uint32_t a[2][4];
#pragma unroll
            for (int mm = 0; mm < 2; mm++)
                ldmatrix_x4(a[mm],
                    st + aoff[mm] + (uint32_t)(((2 * s + ahi) ^ axr[mm]) << 4));
#pragma unroll
            for (int np = 0; np < 4; np++) {
                uint32_t b[4];
                ldmatrix_x4(b,
                    st + 8192 + boff[np] + (uint32_t)(((2 * s + bhi) ^ bxr[np]) << 4));
                mma_f16(d[0][2 * np],     a[0], b[0], b[1]);
                mma_f16(d[1][2 * np],     a[1], b[0], b[1]);
                mma_f16(d[0][2 * np + 1], a[0], b[2], b[3]);
                mma_f16(d[1][2 * np + 1], a[1], b[2], b[3]);
            }
        }
        __syncthreads();
        if (kt + 2 < 8) ISSUE(kt + 2);
    }
#undef ISSUE

    const int g = lane >> 2, c = lane & 3;
#pragma unroll
    for (int nm = 0; nm < 8; nm++) {
        const int col = bn + warpN * 64 + nm * 8 + c * 2;
        const float2 bv = *(const float2*)(bias + col);
#pragma unroll
        for (int mm = 0; mm < 2; mm++) {
            const int r0 = bm + warpM * 32 + mm * 16 + g;
            float2 v0 = { d[mm][nm][0] + bv.x, d[mm][nm][1] + bv.y };
            float2 v1 = { d[mm][nm][2] + bv.x, d[mm][nm][3] + bv.y };
            *(float2*)(C + (long)r0 * N + col)       = v0;
            *(float2*)(C + (long)(r0 + 8) * N + col) = v1;
        }
    }
}

// ---------------------------------------------------------------------------
// Windowed attention, fp16 ldmatrix/mma. One block per (window, head), 256 thr.
//   Kt [256 rows][64B]  swizzled like hgemm B (chunk q ^= (row>>1)&3)
//   VT [32 rows][512B]  V transposed, chunk q ^= (row&7)
//   Qc [32 rows][64B]   Q chunk (hgemm A format)
//   Pc [32 rows][512B]  P as half (A-frag source for PV)
//   SS fp32 [32][264]   S stage / PV partials [8][32][33]
// ---------------------------------------------------------------------------
#define A2_K   0
#define A2_VT  16384
#define A2_Q   32768
#define A2_P   34816
#define A2_SS  51200
#define A2_BYTES 84992

__global__ __launch_bounds__(256, 2)
void attn_h(const float* __restrict__ qkv, __half* __restrict__ o_out,
            float* __restrict__ attn)
{
    extern __shared__ char smem[];
    const uint32_t sb = (uint32_t)__cvta_generic_to_shared(smem);
    float*  SS = (float*)(smem + A2_SS);
    __half* Ph = (__half*)(smem + A2_P);
    __half* VTh = (__half*)(smem + A2_VT);

    const int bid = blockIdx.x;
    const int win = bid >> 3, h = bid & 7;
    const int b = win >> 8, win_y = (win >> 4) & 15, win_x = win & 15;
    const int tid  = threadIdx.x;
    const int lane = tid & 31, w = tid >> 5;
    const int g = lane >> 2, c = lane & 3;

    const long tok_base  = (long)b * 65536 + (long)(win_y * 16) * 256 + win_x * 16;
    const long attn_base = ((long)win * NHEAD + h) * 65536;
    const float scale = 0.17677669529663687f;   // 32^-0.5

    // ---- init: K rows (hgemm format) + V transposed, half ----
    {
        const int t = tid;
        const long gtok = tok_base + (long)(t >> 4) * 256 + (t & 15);
        const float4* src = (const float4*)(qkv + gtok * QKVN + h * HDIM);
        const int xr = (t >> 1) & 3;
#pragma unroll
        for (int q = 0; q < 4; q++) {
            float4 u = src[64 + 2 * q];
            float4 v = src[64 + 2 * q + 1];
            uint4 pk = { packh2(u.x, u.y), packh2(u.z, u.w),
                         packh2(v.x, v.y), packh2(v.z, v.w) };
            *(uint4*)(smem + A2_K + t * 64 + ((q ^ xr) << 4)) = pk;
        }
#pragma unroll
        for (int d4 = 0; d4 < 8; d4++) {
            float4 vv = src[128 + d4];
            float comp[4] = { vv.x, vv.y, vv.z, vv.w };
#pragma unroll
            for (int j = 0; j < 4; j++) {
                const int dd = d4 * 4 + j;
                VTh[dd * 256 + (((t >> 3) ^ (dd & 7)) << 3) + (t & 7)] =
                    __float2half_rn(comp[j]);
            }
        }
    }

    // fragment lane constants
    const int ahi = lane >> 4;
    const int bhi = (lane >> 3) & 1;
    const int fr8 = (lane & 7) + ((lane >> 3) & 1) * 8;   // A-frag row within 16
    uint32_t qoff[2], qxr[2];
    qoff[0] = (uint32_t)fr8 * 64;        qxr[0] = (fr8 >> 1) & 3;
    qoff[1] = (uint32_t)(fr8 + 16) * 64; qxr[1] = ((fr8 + 16) >> 1) & 3;
    int knrow[2]; uint32_t kxr[2];
#pragma unroll
    for (int np = 0; np < 2; np++) {
        knrow[np] = w * 32 + np * 16 + (lane & 7) + (lane >> 4) * 8;
        kxr[np]   = (knrow[np] >> 1) & 3;
    }
    const int prow[2] = { fr8, fr8 + 16 };
    const int vnrow[2] = { (lane & 7) + (lane >> 4) * 8,
                           16 + (lane & 7) + (lane >> 4) * 8 };

    for (int qc = 0; qc < 8; qc++) {
        // ---- load Q chunk (rows qc*32..+31) into hgemm-A format ----
        if (tid < 128) {
            const int row = tid >> 2, q = tid & 3;
            const int rw = qc * 32 + row;
            const long gtok = tok_base + (long)(rw >> 4) * 256 + (rw & 15);
            const float* qp = qkv + gtok * QKVN + h * HDIM + q * 8;
            float4 u = *(const float4*)qp;
            float4 v = *(const float4*)(qp + 4);
            uint4 pk = { packh2(u.x, u.y), packh2(u.z, u.w),
                         packh2(v.x, v.y), packh2(v.z, v.w) };
            *(uint4*)(smem + A2_Q + row * 64 + ((q ^ ((row >> 1) & 3)) << 4)) = pk;
        }
        __syncthreads();                               // (1) Q/K/V ready, SS free

        // ---- S = Qc @ K^T : warp w owns cols [w*32, +32), rows 0..31 ----
        float d[2][4][4];
#pragma unroll
        for (int mm = 0; mm < 2; mm++)
#pragma unroll
            for (int nm = 0; nm < 4; nm++)
#pragma unroll
                for (int q = 0; q < 4; q++) d[mm][nm][q] = 0.f;

#pragma unroll
        for (int s = 0; s < 2; s++) {
            uint32_t a[2][4];
#pragma unroll
            for (int mm = 0; mm < 2; mm++)
                ldmatrix_x4(a[mm],
                    sb + A2_Q + qoff[mm] + (uint32_t)(((2 * s + ahi) ^ qxr[mm]) << 4));
#pragma unroll
            for (int np = 0; np < 2; np++) {
                uint32_t bq[4];
                ldmatrix_x4(bq,
                    sb + A2_K + (uint32_t)knrow[np] * 64 +
                    (uint32_t)(((2 * s + bhi) ^ kxr[np]) << 4));
                mma_f16(d[0][2 * np],     a[0], bq[0], bq[1]);
                mma_f16(d[1][2 * np],     a[1], bq[0], bq[1]);
                mma_f16(d[0][2 * np + 1], a[0], bq[2], bq[3]);
                mma_f16(d[1][2 * np + 1], a[1], bq[2], bq[3]);
            }
        }
        // stage S to SS fp32 (row stride 264, float2-aligned)
#pragma unroll
        for (int mm = 0; mm < 2; mm++)
#pragma unroll
            for (int nm = 0; nm < 4; nm++) {
                float* p = SS + (mm * 16 + g) * 264 + w * 32 + nm * 8 + 2 * c;
                *(float2*)p             = make_float2(d[mm][nm][0], d[mm][nm][1]);
                *(float2*)(p + 8 * 264) = make_float2(d[mm][nm][2], d[mm][nm][3]);
            }
        __syncthreads();                               // (2) S staged

        // ---- softmax: warp w owns rows w*4..+3; write attn fp32 + P half ----
#pragma unroll
        for (int i = 0; i < 4; i++) {
            const int row = w * 4 + i;
            float sv[8];
#pragma unroll
            for (int jj = 0; jj < 8; jj++)
                sv[jj] = SS[row * 264 + jj * 32 + lane] * scale;
            float m = sv[0];
#pragma unroll
            for (int jj = 1; jj < 8; jj++) m = fmaxf(m, sv[jj]);
#pragma unroll
            for (int off = 16; off > 0; off >>= 1)
                m = fmaxf(m, __shfl_xor_sync(0xffffffffu, m, off));
            float l = 0.f;
#pragma unroll
            for (int jj = 0; jj < 8; jj++) { sv[jj] = __expf(sv[jj] - m); l += sv[jj]; }
#pragma unroll
            for (int off = 16; off > 0; off >>= 1)
                l += __shfl_xor_sync(0xffffffffu, l, off);
            const float inv = 1.f / l;
            const long arow = attn_base + (long)(qc * 32 + row) * 256;
#pragma unroll
            for (int jj = 0; jj < 8; jj++) {
                float p = sv[jj] * inv;
                if (attn) __stcs(attn + arow + jj * 32 + lane, p);
                const int phys = (jj * 4 + (lane >> 3)) ^ (row & 7);
                Ph[row * 256 + phys * 8 + (lane & 7)] = __float2half_rn(p);
            }
        }
        __syncthreads();                               // (3) P ready

        // ---- O partial = P[:, w*32:+32] @ V[w*32:+32, :] ----
        float e[2][4][4];
#pragma unroll
        for (int mm = 0; mm < 2; mm++)
#pragma unroll
            for (int nm = 0; nm < 4; nm++)
#pragma unroll
                for (int q = 0; q < 4; q++) e[mm][nm][q] = 0.f;

#pragma unroll
        for (int s = 0; s < 2; s++) {
            const int qch = w * 4 + s * 2;
            uint32_t a[2][4];
#pragma unroll
            for (int mm = 0; mm < 2; mm++)
                ldmatrix_x4(a[mm],
                    sb + A2_P + (uint32_t)prow[mm] * 512 +
                    (uint32_t)(((qch + ahi) ^ (prow[mm] & 7)) << 4));
#pragma unroll
            for (int np = 0; np < 2; np++) {
                uint32_t bq[4];
                ldmatrix_x4(bq,
                    sb + A2_VT + (uint32_t)vnrow[np] * 512 +
                    (uint32_t)(((qch + bhi) ^ (vnrow[np] & 7)) << 4));
                mma_f16(e[0][2 * np],     a[0], bq[0], bq[1]);
                mma_f16(e[1][2 * np],     a[1], bq[0], bq[1]);
                mma_f16(e[0][2 * np + 1], a[0], bq[2], bq[3]);
                mma_f16(e[1][2 * np + 1], a[1], bq[2], bq[3]);
            }
        }

        // partials -> SS as part[w][32][33] (stride 33 odd: scalar stores only)
#pragma unroll
        for (int mm = 0; mm < 2; mm++)
#pragma unroll
            for (int nm = 0; nm < 4; nm++) {
                const int base = w * 1056 + (mm * 16 + g) * 33 + nm * 8 + 2 * c;
                SS[base]              = e[mm][nm][0];
                SS[base + 1]          = e[mm][nm][1];
                SS[base + 8 * 33]     = e[mm][nm][2];
                SS[base + 8 * 33 + 1] = e[mm][nm][3];
            }
        __syncthreads();                               // (4) partials staged

        // ---- reduce 8 partials, store O as half (natural layout) ----
        {
            const int dd = tid & 31;
            const int r0 = (tid >> 5) * 4;
#pragma unroll
            for (int i = 0; i < 4; i++) {
                const int r = r0 + i;
                float acc = 0.f;
#pragma unroll
                for (int wp = 0; wp < 8; wp++)
                    acc += SS[wp * 1056 + r * 33 + dd];
                const int rw = qc * 32 + r;
                const long gtok = tok_base + (long)(rw >> 4) * 256 + (rw & 15);
                o_out[gtok * CDIM + h * HDIM + dd] = __float2half_rn(acc);
            }
        }
        // next iteration's sync (1) protects SS / Qc / Pc reuse
    }
}

// ---------------------------------------------------------------------------
extern "C" void kernel_launch(void* const* d_in, const int* in_sizes, int n_in,
                              void* d_out, int out_size)
{
    (void)in_sizes; (void)n_in;
    const float* x      = (const float*)d_in[0];
    const float* qkv_w  = (const float*)d_in[1];
    const float* qkv_b  = (const float*)d_in[2];
    const float* proj_w = (const float*)d_in[3];
    const float* proj_b = (const float*)d_in[4];

    float*  qkv_buf; __half *oh, *xh, *wq, *wp;
    cudaGetSymbolAddress((void**)&qkv_buf, g_qkv);
    cudaGetSymbolAddress((void**)&oh,      g_oh);
    cudaGetSymbolAddress((void**)&xh,      g_xh);
    cudaGetSymbolAddress((void**)&wq,      g_wq);
    cudaGetSymbolAddress((void**)&wp,      g_wp);

    float* out_ptr  = (float*)d_out;
    float* attn_ptr = nullptr;
    long osz = (long)out_size;
    if (osz >= OUT_ELEMS + ATTN_ELEMS) {
        out_ptr  = (float*)d_out;
        attn_ptr = (float*)d_out + OUT_ELEMS;
    } else if (osz == ATTN_ELEMS) {
        attn_ptr = (float*)d_out;
        out_ptr  = qkv_buf;
    }

    // 0) prep: x -> half; weights -> [N][K] half
    cvt_f16<<<4096, 256>>>(x, xh, OUT_ELEMS / 4);
    transpose_cvt_h<<<dim3(QKVN / 32, CDIM / 32), dim3(32, 8)>>>(qkv_w,  wq, CDIM, QKVN);
    transpose_cvt_h<<<dim3(CDIM / 32, CDIM / 32), dim3(32, 8)>>>(proj_w, wp, CDIM, CDIM);

    // 1) QKV projection (fp16 ldmatrix/mma)
    cudaFuncSetAttribute(hgemm, cudaFuncAttributeMaxDynamicSharedMemorySize, HG_SMEM);
    hgemm<<<dim3(QKVN / 128, (int)(MROWS / 128)), 256, HG_SMEM>>>(
        xh, wq, qkv_b, qkv_buf, QKVN);

    // 2) Windowed attention (fp16 ldmatrix/mma, fp32 softmax)
    cudaFuncSetAttribute(attn_h, cudaFuncAttributeMaxDynamicSharedMemorySize, A2_BYTES);
    attn_h<<<NWIN * NHEAD, 256, A2_BYTES>>>(qkv_buf, oh, attn_ptr);

    // 3) Output projection (fp16 ldmatrix/mma)
    hgemm<<<dim3(CDIM / 128, (int)(MROWS / 128)), 256, HG_SMEM>>>(
        oh, wp, proj_b, out_ptr, CDIM);
}

// round 17
// speedup vs baseline: 2.4510x; 1.0658x over previous
#include <cuda_runtime.h>
#include <cuda_fp16.h>
#include <math.h>
#include <stdint.h>

// ---------------------------------------------------------------------------
// LocalSparseAttention — fp16 end-to-end pipeline (fp32 softmax/accum)
//   B=2, N=65536 (256x256), C=256, window=16 (256 tok/window), heads=8, hd=32
//   qkv intermediate stored as HALF (attn consumes half natively via cp.async)
// ---------------------------------------------------------------------------

#define MROWS 131072L
#define CDIM  256
#define QKVN  768
#define NWIN  512
#define NHEAD 8
#define HDIM  32

static const long OUT_ELEMS  = MROWS * CDIM;                    // 33,554,432
static const long ATTN_ELEMS = (long)NWIN * NHEAD * 256 * 256;  // 268,435,456

__device__ __half g_qkvh[MROWS * QKVN];  // qkv output (half, natural)
__device__ __half g_oh  [MROWS * CDIM];  // attention output (half, natural)
__device__ __half g_xh  [MROWS * CDIM];  // x as half
__device__ __half g_wq  [QKVN * CDIM];   // qkv_w^T  [768][256] half
__device__ __half g_wp  [CDIM * CDIM];   // proj_w^T [256][256] half

// ---- helpers ----
__device__ __forceinline__ void cp_async16(uint32_t dst, const void* src) {
    asm volatile("cp.async.cg.shared.global [%0], [%1], 16;" :: "r"(dst), "l"(src));
}
__device__ __forceinline__ void mma_f16(float* d, const uint32_t* a,
                                        uint32_t b0, uint32_t b1) {
    asm volatile(
        "mma.sync.aligned.m16n8k16.row.col.f32.f16.f16.f32 "
        "{%0,%1,%2,%3}, {%4,%5,%6,%7}, {%8,%9}, {%0,%1,%2,%3};"
        : "+f"(d[0]), "+f"(d[1]), "+f"(d[2]), "+f"(d[3])
        : "r"(a[0]), "r"(a[1]), "r"(a[2]), "r"(a[3]), "r"(b0), "r"(b1));
}
__device__ __forceinline__ void ldmatrix_x4(uint32_t* r, uint32_t addr) {
    asm volatile("ldmatrix.sync.aligned.m8n8.x4.shared.b16 {%0,%1,%2,%3}, [%4];"
                 : "=r"(r[0]), "=r"(r[1]), "=r"(r[2]), "=r"(r[3]) : "r"(addr));
}

// ---------------------------------------------------------------------------
// Prep kernels
// ---------------------------------------------------------------------------
__global__ void cvt_f16(const float* __restrict__ in, __half* __restrict__ out,
                        long n4)
{
    long i = (long)blockIdx.x * blockDim.x + threadIdx.x;
    long stride = (long)gridDim.x * blockDim.x;
    for (; i < n4; i += stride) {
        float4 v = ((const float4*)in)[i];
        __half2 h0 = __floats2half2_rn(v.x, v.y);
        __half2 h1 = __floats2half2_rn(v.z, v.w);
        ((__half2*)out)[2 * i]     = h0;
        ((__half2*)out)[2 * i + 1] = h1;
    }
}

__global__ void transpose_cvt_h(const float* __restrict__ in,
                                __half* __restrict__ out, int K, int N)
{
    __shared__ float t[32][33];
    const int bx = blockIdx.x * 32;   // n
    const int by = blockIdx.y * 32;   // k
    const int x = threadIdx.x, y = threadIdx.y;
    for (int i = y; i < 32; i += 8)
        t[i][x] = in[(long)(by + i) * N + bx + x];
    __syncthreads();
    for (int i = y; i < 32; i += 8)
        out[(long)(bx + i) * K + by + x] = __float2half_rn(t[x][i]);
}

// ---------------------------------------------------------------------------
// fp16 tensor-core GEMM. Output: fp32 (C) or half (Ch) — exactly one non-null.
// ---------------------------------------------------------------------------
#define HG_SMEM 32768

__global__ __launch_bounds__(256, 2)
void hgemm(const __half* __restrict__ A, const __half* __restrict__ BT,
           const float* __restrict__ bias, float* __restrict__ C,
           __half* __restrict__ Ch, int N)
{
    extern __shared__ char smem[];
    const uint32_t sb = (uint32_t)__cvta_generic_to_shared(smem);
    const int tid = threadIdx.x;
    const int bm = blockIdx.y * 128, bn = blockIdx.x * 128;
    const int lane = tid & 31, warp = tid >> 5;
    const int warpM = warp >> 1, warpN = warp & 1;

    const int lrow = tid >> 1;
    const int lq   = (tid & 1) * 2;
    const int lxr  = (lrow >> 1) & 3;
    const uint32_t l_off = (uint32_t)lrow * 64;
    const __half* Ag = A  + (long)(bm + lrow) * 256;
    const __half* Bg = BT + (long)(bn + lrow) * 256;

    const int ahi = lane >> 4;
    const int bhi = (lane >> 3) & 1;
    int arow0 = warpM * 32 + (lane & 7) + ((lane >> 3) & 1) * 8;
    uint32_t aoff[2], axr[2];
    aoff[0] = (uint32_t)arow0 * 64;          axr[0] = (arow0 >> 1) & 3;
    aoff[1] = (uint32_t)(arow0 + 16) * 64;   axr[1] = ((arow0 + 16) >> 1) & 3;
    uint32_t boff[4], bxr[4];
#pragma unroll
    for (int np = 0; np < 4; np++) {
        int nrow = warpN * 64 + np * 16 + (lane & 7) + (lane >> 4) * 8;
        boff[np] = (uint32_t)nrow * 64;
        bxr[np]  = (nrow >> 1) & 3;
    }

    float d[2][8][4];
#pragma unroll
    for (int mm = 0; mm < 2; mm++)
#pragma unroll
        for (int nm = 0; nm < 8; nm++)
#pragma unroll
            for (int q = 0; q < 4; q++) d[mm][nm][q] = 0.f;

#define ISSUE(kt) do {                                                        \
        uint32_t st_ = sb + ((kt) & 1) * 16384;                               \
        const __half* as_ = Ag + (kt) * 32;                                   \
        cp_async16(st_ + l_off + (uint32_t)((lq ^ lxr) << 4),       as_ + lq * 8);      \
        cp_async16(st_ + l_off + (uint32_t)(((lq + 1) ^ lxr) << 4), as_ + lq * 8 + 8);  \
        const __half* bs_ = Bg + (kt) * 32;                                   \
        cp_async16(st_ + 8192 + l_off + (uint32_t)((lq ^ lxr) << 4),       bs_ + lq * 8);     \
        cp_async16(st_ + 8192 + l_off + (uint32_t)(((lq + 1) ^ lxr) << 4), bs_ + lq * 8 + 8); \
        asm volatile("cp.async.commit_group;");                               \
    } while (0)

    ISSUE(0);
    ISSUE(1);

    for (int kt = 0; kt < 8; kt++) {
        if (kt < 6) asm volatile("cp.async.wait_group 1;");
        else        asm volatile("cp.async.wait_group 0;");
        __syncthreads();

        const uint32_t st = sb + (kt & 1) * 16384;
#pragma unroll
        for (int s = 0; s < 2; s++) {
            uint32_t a[2][4];
#pragma unroll
            for (int mm = 0; mm < 2; mm++)
                ldmatrix_x4(a[mm],
                    st + aoff[mm] + (uint32_t)(((2 * s + ahi) ^ axr[mm]) << 4));
#pragma unroll
            for (int np = 0; np < 4; np++) {
                uint32_t b[4];
                ldmatrix_x4(b,
                    st + 8192 + boff[np] + (uint32_t)(((2 * s + bhi) ^ bxr[np]) << 4));
                mma_f16(d[0][2 * np],     a[0], b[0], b[1]);
                mma_f16(d[1][2 * np],     a[1], b[0], b[1]);
                mma_f16(d[0][2 * np + 1], a[0], b[2], b[3]);
                mma_f16(d[1][2 * np + 1], a[1], b[2], b[3]);
            }
        }
        __syncthreads();
        if (kt + 2 < 8) ISSUE(kt + 2);
    }
#undef ISSUE

    const int g = lane >> 2, c = lane & 3;
#pragma unroll
    for (int nm = 0; nm < 8; nm++) {
        const int col = bn + warpN * 64 + nm * 8 + c * 2;
        const float2 bv = *(const float2*)(bias + col);
#pragma unroll
        for (int mm = 0; mm < 2; mm++) {
            const int r0 = bm + warpM * 32 + mm * 16 + g;
            if (Ch) {   // half output (rn from fp32 acc+bias — same as 2-step)
                __half2 h0 = __floats2half2_rn(d[mm][nm][0] + bv.x, d[mm][nm][1] + bv.y);
                __half2 h1 = __floats2half2_rn(d[mm][nm][2] + bv.x, d[mm][nm][3] + bv.y);
                *(uint32_t*)(Ch + (long)r0 * N + col)       = *(uint32_t*)&h0;
                *(uint32_t*)(Ch + (long)(r0 + 8) * N + col) = *(uint32_t*)&h1;
            } else {
                float2 v0 = { d[mm][nm][0] + bv.x, d[mm][nm][1] + bv.y };
                float2 v1 = { d[mm][nm][2] + bv.x, d[mm][nm][3] + bv.y };
                *(float2*)(C + (long)r0 * N + col)       = v0;
                *(float2*)(C + (long)(r0 + 8) * N + col) = v1;
            }
        }
    }
}

// ---------------------------------------------------------------------------
// Windowed attention, fp16 ldmatrix/mma, half qkv input via cp.async.
//   Kt [256 rows][64B]  swizzled (chunk q ^= (row>>1)&3)  — direct cp.async
//   VT [32 rows][512B]  V transposed, chunk q ^= (row&7)  — manual scatter
//   Qc [32 rows][64B]   Q chunk — direct cp.async
//   Pc [32 rows][512B]  P half (A-frag source for PV)
//   SS fp32 [32][264]   S stage / PV partials [8][32][33]
// ---------------------------------------------------------------------------
#define A2_K   0
#define A2_VT  16384
#define A2_Q   32768
#define A2_P   34816
#define A2_SS  51200
#define A2_BYTES 84992

__global__ __launch_bounds__(256, 2)
void attn_h(const __half* __restrict__ qkv, __half* __restrict__ o_out,
            float* __restrict__ attn)
{
    extern __shared__ char smem[];
    const uint32_t sb = (uint32_t)__cvta_generic_to_shared(smem);
    float*  SS = (float*)(smem + A2_SS);
    __half* Ph = (__half*)(smem + A2_P);
    __half* VTh = (__half*)(smem + A2_VT);

    const int bid = blockIdx.x;
    const int win = bid >> 3, h = bid & 7;
    const int b = win >> 8, win_y = (win >> 4) & 15, win_x = win & 15;
    const int tid  = threadIdx.x;
    const int lane = tid & 31, w = tid >> 5;
    const int g = lane >> 2, c = lane & 3;

    const long tok_base  = (long)b * 65536 + (long)(win_y * 16) * 256 + win_x * 16;
    const long attn_base = ((long)win * NHEAD + h) * 65536;
    const float scale = 0.17677669529663687f;   // 32^-0.5

    // ---- init: K rows via cp.async (swizzled) + V transposed scatter ----
    {
        const int t = tid;
        const long gtok = tok_base + (long)(t >> 4) * 256 + (t & 15);
        const __half* krow = qkv + gtok * QKVN + 256 + h * HDIM;
        const int xr = (t >> 1) & 3;
#pragma unroll
        for (int q = 0; q < 4; q++)
            cp_async16(sb + A2_K + t * 64 + (uint32_t)((q ^ xr) << 4), krow + q * 8);
        asm volatile("cp.async.commit_group;");

        // V: 32 half per token -> transposed scatter
        uint4 raw[4];
        const uint4* vsrc = (const uint4*)(qkv + gtok * QKVN + 512 + h * HDIM);
#pragma unroll
        for (int q = 0; q < 4; q++) raw[q] = vsrc[q];
        const __half* vh = (const __half*)raw;
#pragma unroll
        for (int dd = 0; dd < 32; dd++)
            VTh[dd * 256 + (((t >> 3) ^ (dd & 7)) << 3) + (t & 7)] = vh[dd];
    }

    // fragment lane constants
    const int ahi = lane >> 4;
    const int bhi = (lane >> 3) & 1;
    const int fr8 = (lane & 7) + ((lane >> 3) & 1) * 8;
    uint32_t qoff[2], qxr[2];
    qoff[0] = (uint32_t)fr8 * 64;        qxr[0] = (fr8 >> 1) & 3;
    qoff[1] = (uint32_t)(fr8 + 16) * 64; qxr[1] = ((fr8 + 16) >> 1) & 3;
    int knrow[2]; uint32_t kxr[2];
#pragma unroll
    for (int np = 0; np < 2; np++) {
        knrow[np] = w * 32 + np * 16 + (lane & 7) + (lane >> 4) * 8;
        kxr[np]   = (knrow[np] >> 1) & 3;
    }
    const int prow[2] = { fr8, fr8 + 16 };
    const int vnrow[2] = { (lane & 7) + (lane >> 4) * 8,
                           16 + (lane & 7) + (lane >> 4) * 8 };

    for (int qc = 0; qc < 8; qc++) {
        // ---- load Q chunk via cp.async (rows qc*32..+31, hgemm-A format) ----
        if (tid < 128) {
            const int row = tid >> 2, q = tid & 3;
            const int rw = qc * 32 + row;
            const long gtok = tok_base + (long)(rw >> 4) * 256 + (rw & 15);
            cp_async16(sb + A2_Q + row * 64 + (uint32_t)((q ^ ((row >> 1) & 3)) << 4),
                       qkv + gtok * QKVN + h * HDIM + q * 8);
        }
        asm volatile("cp.async.commit_group;");
        asm volatile("cp.async.wait_group 0;");
        __syncthreads();                               // (1) Q/K/V ready, SS free

        // ---- S = Qc @ K^T : warp w owns cols [w*32, +32) ----
        float d[2][4][4];
#pragma unroll
        for (int mm = 0; mm < 2; mm++)
#pragma unroll
            for (int nm = 0; nm < 4; nm++)
#pragma unroll
                for (int q = 0; q < 4; q++) d[mm][nm][q] = 0.f;

#pragma unroll
        for (int s = 0; s < 2; s++) {
            uint32_t a[2][4];
#pragma unroll
            for (int mm = 0; mm < 2; mm++)
                ldmatrix_x4(a[mm],
                    sb + A2_Q + qoff[mm] + (uint32_t)(((2 * s + ahi) ^ qxr[mm]) << 4));
#pragma unroll
            for (int np = 0; np < 2; np++) {
                uint32_t bq[4];
                ldmatrix_x4(bq,
                    sb + A2_K + (uint32_t)knrow[np] * 64 +
                    (uint32_t)(((2 * s + bhi) ^ kxr[np]) << 4));
                mma_f16(d[0][2 * np],     a[0], bq[0], bq[1]);
                mma_f16(d[1][2 * np],     a[1], bq[0], bq[1]);
                mma_f16(d[0][2 * np + 1], a[0], bq[2], bq[3]);
                mma_f16(d[1][2 * np + 1], a[1], bq[2], bq[3]);
            }
        }
#pragma unroll
        for (int mm = 0; mm < 2; mm++)
#pragma unroll
            for (int nm = 0; nm < 4; nm++) {
                float* p = SS + (mm * 16 + g) * 264 + w * 32 + nm * 8 + 2 * c;
                *(float2*)p             = make_float2(d[mm][nm][0], d[mm][nm][1]);
                *(float2*)(p + 8 * 264) = make_float2(d[mm][nm][2], d[mm][nm][3]);
            }
        __syncthreads();                               // (2) S staged

        // ---- softmax: warp w owns rows w*4..+3; write attn fp32 + P half ----
#pragma unroll
        for (int i = 0; i < 4; i++) {
            const int row = w * 4 + i;
            float sv[8];
#pragma unroll
            for (int jj = 0; jj < 8; jj++)
                sv[jj] = SS[row * 264 + jj * 32 + lane] * scale;
            float m = sv[0];
#pragma unroll
            for (int jj = 1; jj < 8; jj++) m = fmaxf(m, sv[jj]);
#pragma unroll
            for (int off = 16; off > 0; off >>= 1)
                m = fmaxf(m, __shfl_xor_sync(0xffffffffu, m, off));
            float l = 0.f;
#pragma unroll
            for (int jj = 0; jj < 8; jj++) { sv[jj] = __expf(sv[jj] - m); l += sv[jj]; }
#pragma unroll
            for (int off = 16; off > 0; off >>= 1)
                l += __shfl_xor_sync(0xffffffffu, l, off);
            const float inv = 1.f / l;
            const long arow = attn_base + (long)(qc * 32 + row) * 256;
#pragma unroll
            for (int jj = 0; jj < 8; jj++) {
                float p = sv[jj] * inv;
                if (attn) __stcs(attn + arow + jj * 32 + lane, p);
                const int phys = (jj * 4 + (lane >> 3)) ^ (row & 7);
                Ph[row * 256 + phys * 8 + (lane & 7)] = __float2half_rn(p);
            }
        }
        __syncthreads();                               // (3) P ready

        // ---- O partial = P[:, w*32:+32] @ V[w*32:+32, :] ----
        float e[2][4][4];
#pragma unroll
        for (int mm = 0; mm < 2; mm++)
#pragma unroll
            for (int nm = 0; nm < 4; nm++)
#pragma unroll
                for (int q = 0; q < 4; q++) e[mm][nm][q] = 0.f;

#pragma unroll
        for (int s = 0; s < 2; s++) {
            const int qch = w * 4 + s * 2;
            uint32_t a[2][4];
#pragma unroll
            for (int mm = 0; mm < 2; mm++)
                ldmatrix_x4(a[mm],
                    sb + A2_P + (uint32_t)prow[mm] * 512 +
                    (uint32_t)(((qch + ahi) ^ (prow[mm] & 7)) << 4));
#pragma unroll
            for (int np = 0; np < 2; np++) {
                uint32_t bq[4];
                ldmatrix_x4(bq,
                    sb + A2_VT + (uint32_t)vnrow[np] * 512 +
                    (uint32_t)(((qch + bhi) ^ (vnrow[np] & 7)) << 4));
                mma_f16(e[0][2 * np],     a[0], bq[0], bq[1]);
                mma_f16(e[1][2 * np],     a[1], bq[0], bq[1]);
                mma_f16(e[0][2 * np + 1], a[0], bq[2], bq[3]);
                mma_f16(e[1][2 * np + 1], a[1], bq[2], bq[3]);
            }
        }

        // partials -> SS as part[w][32][33] (stride 33 odd: scalar stores only)
#pragma unroll
        for (int mm = 0; mm < 2; mm++)
#pragma unroll
            for (int nm = 0; nm < 4; nm++) {
                const int base = w * 1056 + (mm * 16 + g) * 33 + nm * 8 + 2 * c;
                SS[base]              = e[mm][nm][0];
                SS[base + 1]          = e[mm][nm][1];
                SS[base + 8 * 33]     = e[mm][nm][2];
                SS[base + 8 * 33 + 1] = e[mm][nm][3];
            }
        __syncthreads();                               // (4) partials staged

        // ---- reduce 8 partials, store O as half ----
        {
            const int dd = tid & 31;
            const int r0 = (tid >> 5) * 4;
#pragma unroll
            for (int i = 0; i < 4; i++) {
                const int r = r0 + i;
                float acc = 0.f;
#pragma unroll
                for (int wp = 0; wp < 8; wp++)
                    acc += SS[wp * 1056 + r * 33 + dd];
                const int rw = qc * 32 + r;
                const long gtok = tok_base + (long)(rw >> 4) * 256 + (rw & 15);
                o_out[gtok * CDIM + h * HDIM + dd] = __float2half_rn(acc);
            }
        }
        // next iteration's sync (1) protects SS / Qc / Pc reuse
    }
}

// ---------------------------------------------------------------------------
extern "C" void kernel_launch(void* const* d_in, const int* in_sizes, int n_in,
                              void* d_out, int out_size)
{
    (void)in_sizes; (void)n_in;
    const float* x      = (const float*)d_in[0];
    const float* qkv_w  = (const float*)d_in[1];
    const float* qkv_b  = (const float*)d_in[2];
    const float* proj_w = (const float*)d_in[3];
    const float* proj_b = (const float*)d_in[4];

    __half *qkvh, *oh, *xh, *wq, *wp;
    cudaGetSymbolAddress((void**)&qkvh, g_qkvh);
    cudaGetSymbolAddress((void**)&oh,   g_oh);
    cudaGetSymbolAddress((void**)&xh,   g_xh);
    cudaGetSymbolAddress((void**)&wq,   g_wq);
    cudaGetSymbolAddress((void**)&wp,   g_wp);

    float* out_ptr  = (float*)d_out;
    float* attn_ptr = nullptr;
    long osz = (long)out_size;
    if (osz >= OUT_ELEMS + ATTN_ELEMS) {
        out_ptr  = (float*)d_out;
        attn_ptr = (float*)d_out + OUT_ELEMS;
    } else if (osz == ATTN_ELEMS) {
        attn_ptr = (float*)d_out;
        // qkv bytes (201MB) already consumed by attn before proj runs; reuse as
        // fp32 scratch (needs 134MB)
        out_ptr  = (float*)qkvh;
    }

    // 0) prep: x -> half; weights -> [N][K] half
    cvt_f16<<<4096, 256>>>(x, xh, OUT_ELEMS / 4);
    transpose_cvt_h<<<dim3(QKVN / 32, CDIM / 32), dim3(32, 8)>>>(qkv_w,  wq, CDIM, QKVN);
    transpose_cvt_h<<<dim3(CDIM / 32, CDIM / 32), dim3(32, 8)>>>(proj_w, wp, CDIM, CDIM);

    // 1) QKV projection -> half output
    cudaFuncSetAttribute(hgemm, cudaFuncAttributeMaxDynamicSharedMemorySize, HG_SMEM);
    hgemm<<<dim3(QKVN / 128, (int)(MROWS / 128)), 256, HG_SMEM>>>(
        xh, wq, qkv_b, nullptr, qkvh, QKVN);

    // 2) Windowed attention (half in, half o out, fp32 attn out)
    cudaFuncSetAttribute(attn_h, cudaFuncAttributeMaxDynamicSharedMemorySize, A2_BYTES);
    attn_h<<<NWIN * NHEAD, 256, A2_BYTES>>>(qkvh, oh, attn_ptr);

    // 3) Output projection -> fp32 output
    hgemm<<<dim3(CDIM / 128, (int)(MROWS / 128)), 256, HG_SMEM>>>(
        oh, wp, proj_b, out_ptr, nullptr, CDIM);
}